// round 14
// baseline (speedup 1.0000x reference)
#include <cuda_runtime.h>
#include <math.h>
#include <stdint.h>

// ---------------- problem dims ----------------
#define Bb    8
#define Nn    1024
#define Kk    32
#define Dd    256
#define Hh    8
#define DHh   32
#define TDIMc 16
#define NBc   32
#define HIDc  128
#define Lc    4
#define NSc   128
#define SHDc  9
#define EINc  304
#define Mm    (Bb*Nn)
#define WIN   8

// ---------------- scratch (device globals; no allocs allowed) ----------------
__device__ int   g_src [Mm*Kk];
__device__ float g_cutb[Mm*Kk];
__device__ int   g_win [Mm*Kk];
__device__ float g_sh  [Mm*Kk*SHDc];
__device__ float g_rbf [Mm*Kk*WIN];
__device__ float g_node[Mm*Dd];
__device__ float g_qv  [Mm*512];
__device__ float g_ss  [Mm*256];
__device__ float g_agg [Mm*Dd];
__device__ float g_qk  [Mm*Hh*HIDc];
__device__ float g_tpart[Lc*Bb*HIDc];
__device__ uint32_t g_wcat1[Lc*256*512]; // tf32 [l][k][ Wq | Wv_top ]
__device__ uint32_t g_wcat2[Lc*128*256]; // tf32 [l][k][ Wk1_src | Wk1_dst ]
__device__ uint32_t g_wcat3[3*256*256];  // tf32 [l][k][ Wo ]

// ---------------- FFMA-only fast math ----------------
__device__ __forceinline__ float fast_rcp(float q) {
    float r = __int_as_float(0x7EF311C3 - __float_as_int(q));
    r = r * (2.0f - q * r);
    r = r * (2.0f - q * r);
    r = r * (2.0f - q * r);
    return r;
}
__device__ __forceinline__ float tanh_fast(float x) {
    x = fminf(fmaxf(x, -7.90531110591f), 7.90531110591f);
    float x2 = x * x;
    float p = fmaf(x2, -2.76076847742355e-16f, 2.00018790482477e-13f);
    p = fmaf(x2, p, -8.60467152213735e-11f);
    p = fmaf(x2, p,  5.12229709037114e-08f);
    p = fmaf(x2, p,  1.48572235717979e-05f);
    p = fmaf(x2, p,  6.37261928875436e-04f);
    p = fmaf(x2, p,  4.89352455891786e-03f);
    p = p * x;
    float q = fmaf(x2, 1.19825839466702e-06f, 1.18534705686654e-04f);
    q = fmaf(x2, q, 2.26843463243900e-03f);
    q = fmaf(x2, q, 4.89352518554385e-03f);
    return p * fast_rcp(q);
}
__device__ __forceinline__ float gelu_fast(float v) {
    float c = v * fmaf(v * v, 0.0356774081363f, 0.7978845608028654f);
    return 0.5f * v * (1.0f + tanh_fast(c));
}
__device__ __forceinline__ float exp_fast(float x) {
    x = fmaxf(x, -80.0f);
    float y = x * 1.4426950408889634f;
    float n = floorf(y);
    float f = y - n;
    float p = 1.5252733804059838e-5f;
    p = fmaf(p, f, 1.5403530393381606e-4f);
    p = fmaf(p, f, 1.3333558146428443e-3f);
    p = fmaf(p, f, 9.618129107628477e-3f);
    p = fmaf(p, f, 5.550410866482158e-2f);
    p = fmaf(p, f, 2.402265069591007e-1f);
    p = fmaf(p, f, 6.931471805599453e-1f);
    p = fmaf(p, f, 1.0f);
    return p * __int_as_float(((int)n + 127) << 23);
}
__device__ __forceinline__ uint32_t f2tf32(float f) {
    uint32_t u;
    asm("cvt.rna.tf32.f32 %0, %1;" : "=r"(u) : "f"(f));
    return u;
}
__device__ __forceinline__ void mma_tf32(float c[4], uint32_t a0, uint32_t a1,
                                         uint32_t a2, uint32_t a3,
                                         uint32_t b0, uint32_t b1) {
    asm volatile(
        "mma.sync.aligned.m16n8k8.row.col.f32.tf32.tf32.f32 "
        "{%0,%1,%2,%3}, {%4,%5,%6,%7}, {%8,%9}, {%0,%1,%2,%3};"
        : "+f"(c[0]), "+f"(c[1]), "+f"(c[2]), "+f"(c[3])
        : "r"(a0), "r"(a1), "r"(a2), "r"(a3), "r"(b0), "r"(b1));
}

// ---------------- warp-collective kNN ----------------
__global__ void knn_kernel(const float* __restrict__ x) {
    __shared__ float px[Nn], py[Nn], pz[Nn];
    int b = blockIdx.y;
    const float* xb = x + (size_t)b * Nn * 3;
    for (int i = threadIdx.x; i < Nn; i += blockDim.x) {
        px[i] = xb[i*3+0]; py[i] = xb[i*3+1]; pz[i] = xb[i*3+2];
    }
    __syncthreads();
    int warp = threadIdx.x >> 5, lane = threadIdx.x & 31;
    int n = blockIdx.x * 8 + warp;
    float qx = px[n], qy = py[n], qz = pz[n];

    float dx = qx - px[lane], dy = qy - py[lane], dz = qz - pz[lane];
    float best_d = dx*dx + dy*dy + dz*dz;
    int   best_i = lane;
    float thr = best_d;
    #pragma unroll
    for (int off = 16; off; off >>= 1) thr = fmaxf(thr, __shfl_xor_sync(~0u, thr, off));

    for (int j0 = 32; j0 < Nn; j0 += 32) {
        int j = j0 + lane;
        dx = qx - px[j]; dy = qy - py[j]; dz = qz - pz[j];
        float d2 = dx*dx + dy*dy + dz*dz;
        unsigned mask = __ballot_sync(~0u, d2 < thr);
        while (mask) {
            int src = __ffs(mask) - 1; mask &= mask - 1;
            float cd = __shfl_sync(~0u, d2, src);
            int   ci = j0 + src;
            float m = best_d; int ml = lane;
            #pragma unroll
            for (int off = 16; off; off >>= 1) {
                float om = __shfl_xor_sync(~0u, m, off);
                int  oml = __shfl_xor_sync(~0u, ml, off);
                if (om > m || (om == m && oml > ml)) { m = om; ml = oml; }
            }
            if (cd < m) {
                if (lane == ml) { best_d = cd; best_i = ci; }
            }
            thr = m;
        }
    }
    g_src[(b * Nn + n) * Kk + lane] = best_i;
}

// ---------------- per-edge geometry ----------------
__global__ void geom_kernel(const float* __restrict__ x) {
    int gid = blockIdx.x * blockDim.x + threadIdx.x;
    if (gid >= Mm * Kk) return;
    int m = gid / Kk;
    int b = m / Nn, n = m % Nn;
    int s = g_src[gid];
    const float* xb = x + (size_t)b * Nn * 3;
    float vx = xb[n*3+0] - xb[s*3+0];
    float vy = xb[n*3+1] - xb[s*3+1];
    float vz = xb[n*3+2] - xb[s*3+2];
    float r = sqrtf(vx*vx + vy*vy + vz*vz);
    float xc = 10.0f - 5.0f * r;
    float cut = (xc > 0.0f) ? 1.4f * exp_fast(-fast_rcp(xc)) : 0.0f;
    g_cutb[gid] = cut;
    float inv = 1.0f / fmaxf(r, 1e-9f);
    float ux = vx * inv, uy = vy * inv, uz = vz * inv;
    const float s3 = 1.7320508075688772f;
    const float s15 = 3.872983346207417f;
    const float h5 = 1.118033988749895f;
    const float h15 = 1.9364916731037085f;
    float* sh = g_sh + (size_t)gid * SHDc;
    sh[0] = 1.0f;
    sh[1] = s3 * ux; sh[2] = s3 * uy; sh[3] = s3 * uz;
    sh[4] = s15 * ux * uy;
    sh[5] = s15 * uy * uz;
    sh[6] = h5 * (3.0f * uz * uz - 1.0f);
    sh[7] = s15 * ux * uz;
    sh[8] = h15 * (ux * ux - uy * uy);
    const float ISTEP = 15.5f;
    const float RBFC  = 5.656854249492381f * 0.95f / 1.12f;
    float base = r * ISTEP;
    int i0 = (int)floorf(base) - 3;
    i0 = max(0, min(24, i0));
    g_win[gid] = i0;
    float rb[WIN];
    #pragma unroll
    for (int w = 0; w < WIN; w++) {
        float d = base - (float)(i0 + w);
        rb[w] = exp_fast(-d * d) * RBFC * cut;
    }
    float4* dst = (float4*)(g_rbf + (size_t)gid * WIN);
    dst[0] = make_float4(rb[0], rb[1], rb[2], rb[3]);
    dst[1] = make_float4(rb[4], rb[5], rb[6], rb[7]);
}

// ---------------- node embedding ----------------
__global__ void embed_kernel(const float* __restrict__ y, const float* __restrict__ t,
                             const float* __restrict__ W_embed) {
    __shared__ float in[3 + TDIMc];
    int m = blockIdx.x;
    int b = m / Nn;
    int tid = threadIdx.x;
    if (tid < 3) in[tid] = y[(size_t)m * 3 + tid];
    else if (tid < 3 + TDIMc) in[tid] = t[b * TDIMc + (tid - 3)];
    __syncthreads();
    float acc = 0.0f;
    #pragma unroll
    for (int i = 0; i < 3 + TDIMc; i++) acc += in[i] * W_embed[i * Dd + tid];
    g_node[(size_t)m * Dd + tid] = acc;
}

// ---------------- tpart ----------------
__global__ void tpart_kernel(const float* __restrict__ t, const float* __restrict__ Wk1,
                             const float* __restrict__ bk1) {
    int l = blockIdx.x / Bb, b = blockIdx.x % Bb;
    int j = threadIdx.x;
    float acc = bk1[l * HIDc + j];
    #pragma unroll
    for (int i = 0; i < TDIMc; i++)
        acc += t[b * TDIMc + i] * Wk1[((size_t)l * EINc + 32 + i) * HIDc + j];
    g_tpart[(l * Bb + b) * HIDc + j] = acc;
}

// ---------------- pack weights -> tf32 ----------------
__global__ void pack_kernel(const float* __restrict__ Wq, const float* __restrict__ Wv,
                            const float* __restrict__ Wk1, const float* __restrict__ Wo) {
    int i = blockIdx.x * 256 + threadIdx.x;
    const int SZ1 = Lc * 256 * 512;
    const int SZ2 = Lc * 128 * 256;
    if (i < SZ1) {
        int l = i / (256 * 512);
        int r = (i >> 9) & 255;
        int n = i & 511;
        float v = (n < 256) ? Wq[((size_t)l * 256 + r) * 256 + n]
                            : Wv[((size_t)l * (Dd + SHDc) + r) * 256 + (n - 256)];
        g_wcat1[i] = f2tf32(v);
    } else if (i < SZ1 + SZ2) {
        int j = i - SZ1;
        int l = j / (128 * 256);
        int r = (j >> 8) & 127;
        int n = j & 255;
        int row = (n < 128) ? (48 + r) : (176 + r);
        g_wcat2[j] = f2tf32(Wk1[((size_t)l * EINc + row) * HIDc + (n & 127)]);
    } else {
        int j = i - SZ1 - SZ2;
        if (j < 3 * 256 * 256) g_wcat3[j] = f2tf32(Wo[j]);
    }
}

// ---------------- TF32 TC GEMM, register-prefetch pipelined ----------------
__global__ void __launch_bounds__(256, 2)
gemm_tc(const float* __restrict__ A, int lda,
        const uint32_t* __restrict__ W, int ldw,
        float* __restrict__ C, int ldc, int Kd,
        const float* __restrict__ resid, int actmode) {
    __shared__ uint32_t sA[32 * 132];
    __shared__ uint32_t sB[32 * 132];
    int m0 = blockIdx.x * 128, n0 = blockIdx.y * 128;
    int tid = threadIdx.x, lane = tid & 31, wid = tid >> 5;
    int wm = (wid & 1) * 64, wn = (wid >> 1) * 32;
    int gp = lane >> 2, tg = lane & 3;

    int amm[4], akq[4], bkk[4], bnq[4];
    #pragma unroll
    for (int u = 0; u < 4; u++) {
        int id = tid + u * 256;
        amm[u] = id >> 3; akq[u] = (id & 7) * 4;
        bkk[u] = id >> 5; bnq[u] = (id & 31) * 4;
    }

    float c[4][4][4];
    #pragma unroll
    for (int i = 0; i < 4; i++)
        #pragma unroll
        for (int j = 0; j < 4; j++)
            #pragma unroll
            for (int r = 0; r < 4; r++) c[i][j][r] = 0.0f;

    float4 pa[4];
    uint4  pb[4];
    #pragma unroll
    for (int u = 0; u < 4; u++) {
        pa[u] = *(const float4*)&A[(size_t)(m0 + amm[u]) * lda + akq[u]];
        pb[u] = *(const uint4*)&W[(size_t)bkk[u] * ldw + n0 + bnq[u]];
    }

    for (int kt = 0; kt < Kd; kt += 32) {
        #pragma unroll
        for (int u = 0; u < 4; u++) {
            sA[(akq[u] + 0) * 132 + amm[u]] = f2tf32(pa[u].x);
            sA[(akq[u] + 1) * 132 + amm[u]] = f2tf32(pa[u].y);
            sA[(akq[u] + 2) * 132 + amm[u]] = f2tf32(pa[u].z);
            sA[(akq[u] + 3) * 132 + amm[u]] = f2tf32(pa[u].w);
            *(uint4*)&sB[bkk[u] * 132 + bnq[u]] = pb[u];
        }
        __syncthreads();
        if (kt + 32 < Kd) {
            #pragma unroll
            for (int u = 0; u < 4; u++) {
                pa[u] = *(const float4*)&A[(size_t)(m0 + amm[u]) * lda + kt + 32 + akq[u]];
                pb[u] = *(const uint4*)&W[(size_t)(kt + 32 + bkk[u]) * ldw + n0 + bnq[u]];
            }
        }
        #pragma unroll
        for (int ka = 0; ka < 4; ka++) {
            int kb = ka * 8;
            uint32_t bf[4][2];
            #pragma unroll
            for (int na = 0; na < 4; na++) {
                bf[na][0] = sB[(kb + tg) * 132 + wn + na * 8 + gp];
                bf[na][1] = sB[(kb + tg + 4) * 132 + wn + na * 8 + gp];
            }
            #pragma unroll
            for (int ma = 0; ma < 4; ma++) {
                int mb = wm + ma * 16 + gp;
                uint32_t a0 = sA[(kb + tg) * 132 + mb];
                uint32_t a1 = sA[(kb + tg) * 132 + mb + 8];
                uint32_t a2 = sA[(kb + tg + 4) * 132 + mb];
                uint32_t a3 = sA[(kb + tg + 4) * 132 + mb + 8];
                #pragma unroll
                for (int na = 0; na < 4; na++)
                    mma_tf32(c[ma][na], a0, a1, a2, a3, bf[na][0], bf[na][1]);
            }
        }
        __syncthreads();
    }

    #pragma unroll
    for (int ma = 0; ma < 4; ma++) {
        int row = m0 + wm + ma * 16 + gp;
        #pragma unroll
        for (int na = 0; na < 4; na++) {
            int col = n0 + wn + na * 8 + 2 * tg;
            #pragma unroll
            for (int half = 0; half < 2; half++) {
                int rr = row + half * 8;
                float v0 = c[ma][na][half * 2 + 0];
                float v1 = c[ma][na][half * 2 + 1];
                if (actmode == 1) {
                    float2 rs = *(const float2*)&resid[(size_t)rr * ldc + col];
                    v0 += rs.x; v1 += rs.y;
                    if (col < 64)       { v0 = gelu_fast(v0); v1 = gelu_fast(v1); }
                    else if (col < 128) { v0 = tanh_fast(v0); v1 = tanh_fast(v1); }
                }
                float2 o = make_float2(v0, v1);
                *(float2*)&C[(size_t)rr * ldc + col] = o;
            }
        }
    }
}

// ---------------- qk on tensor cores: per head, 128m x 128j x 32k ----------------
__global__ void qk_tc(const float* __restrict__ Wk2, int l) {
    __shared__ uint32_t sA[32 * 132];
    __shared__ uint32_t sB[32 * 132];
    int m0 = blockIdx.x * 128;
    int h  = blockIdx.y;
    int tid = threadIdx.x, lane = tid & 31, wid = tid >> 5;
    int wm = (wid & 1) * 64, wn = (wid >> 1) * 32;
    int gp = lane >> 2, tg = lane & 3;
    const float* W = Wk2 + (size_t)l * HIDc * Dd;

    #pragma unroll
    for (int u = 0; u < 4; u++) {
        int id = tid + u * 256;
        int mm = id >> 3, kq = (id & 7) * 4;
        float4 v = *(const float4*)&g_qv[(size_t)(m0 + mm) * 512 + h * 32 + kq];
        sA[(kq + 0) * 132 + mm] = f2tf32(v.x);
        sA[(kq + 1) * 132 + mm] = f2tf32(v.y);
        sA[(kq + 2) * 132 + mm] = f2tf32(v.z);
        sA[(kq + 3) * 132 + mm] = f2tf32(v.w);
    }
    #pragma unroll
    for (int u = 0; u < 4; u++) {
        int id = tid + u * 256;
        int j = id >> 3, kq = (id & 7) * 4;
        float4 v = *(const float4*)&W[(size_t)j * 256 + h * 32 + kq];
        sB[(kq + 0) * 132 + j] = f2tf32(v.x);
        sB[(kq + 1) * 132 + j] = f2tf32(v.y);
        sB[(kq + 2) * 132 + j] = f2tf32(v.z);
        sB[(kq + 3) * 132 + j] = f2tf32(v.w);
    }
    __syncthreads();

    float c[4][4][4];
    #pragma unroll
    for (int i = 0; i < 4; i++)
        #pragma unroll
        for (int j = 0; j < 4; j++)
            #pragma unroll
            for (int r = 0; r < 4; r++) c[i][j][r] = 0.0f;

    #pragma unroll
    for (int ka = 0; ka < 4; ka++) {
        int kb = ka * 8;
        uint32_t bf[4][2];
        #pragma unroll
        for (int na = 0; na < 4; na++) {
            bf[na][0] = sB[(kb + tg) * 132 + wn + na * 8 + gp];
            bf[na][1] = sB[(kb + tg + 4) * 132 + wn + na * 8 + gp];
        }
        #pragma unroll
        for (int ma = 0; ma < 4; ma++) {
            int mb = wm + ma * 16 + gp;
            uint32_t a0 = sA[(kb + tg) * 132 + mb];
            uint32_t a1 = sA[(kb + tg) * 132 + mb + 8];
            uint32_t a2 = sA[(kb + tg + 4) * 132 + mb];
            uint32_t a3 = sA[(kb + tg + 4) * 132 + mb + 8];
            #pragma unroll
            for (int na = 0; na < 4; na++)
                mma_tf32(c[ma][na], a0, a1, a2, a3, bf[na][0], bf[na][1]);
        }
    }

    #pragma unroll
    for (int ma = 0; ma < 4; ma++) {
        int row = m0 + wm + ma * 16 + gp;
        #pragma unroll
        for (int na = 0; na < 4; na++) {
            int col = wn + na * 8 + 2 * tg;
            #pragma unroll
            for (int half = 0; half < 2; half++) {
                int rr = row + half * 8;
                float2 o = make_float2(c[ma][na][half * 2 + 0], c[ma][na][half * 2 + 1]);
                *(float2*)&g_qk[(size_t)rr * 1024 + h * 128 + col] = o;
            }
        }
    }
}

// ---------------- fused edge kernel: low-register per-ki pipeline ----------------
__global__ void __launch_bounds__(256, 3)
edge_kernel(const float* __restrict__ Wk1, const float* __restrict__ Wv, int l) {
    __shared__ float s_wk1[32 * 128];
    __shared__ float s_rbf[32 * 8];
    __shared__ float s_qk [8 * 132];
    __shared__ float s_al [32 * 8];
    __shared__ float s_shl[32 * 9];
    __shared__ float s_wvsh[9 * 256];
    __shared__ float s_asum[Hh * SHDc];
    __shared__ float s_base[128];
    __shared__ float s_cut[32];
    __shared__ int   s_id[32];
    __shared__ int   s_i0[32];

    int m = blockIdx.x;
    int b = m >> 10;
    int tid = threadIdx.x;
    const float* Wk1l = Wk1 + (size_t)l * EINc * HIDc;
    const float* WvSh = Wv + ((size_t)l * (Dd + SHDc) + Dd) * Dd;
    const float* tpl  = g_tpart + (l * Bb + b) * HIDc;

    if (tid < 32) {
        s_id[tid]  = g_src [m * 32 + tid];
        s_cut[tid] = g_cutb[m * 32 + tid];
        s_i0[tid]  = g_win [m * 32 + tid];
    }
    if (tid < 128) s_base[tid] = g_ss[(size_t)m * 256 + 128 + tid] + tpl[tid];
    for (int i = tid; i < 1024; i += 256) {
        int h = i >> 7, j = i & 127;
        s_qk[h * 132 + j] = g_qk[(size_t)m * 1024 + i];
    }
    for (int i = tid; i < 32 * SHDc; i += 256) s_shl[i] = g_sh[(size_t)m * 32 * SHDc + i];
    if (tid < 64)
        *(float4*)&s_rbf[tid * 4] = *(const float4*)&g_rbf[(size_t)m * 256 + tid * 4];
    #pragma unroll
    for (int u = 0; u < 4; u++) {
        int idx = (tid + u * 256) * 4;
        *(float4*)&s_wk1[idx] = *(const float4*)&Wk1l[idx];
    }
    #pragma unroll
    for (int u = 0; u < 3; u++) {
        int i = tid + u * 256;
        if (i < 576) *(float4*)&s_wvsh[i * 4] = *(const float4*)&WvSh[i * 4];
    }
    __syncthreads();

    int lane = tid & 31, wid = tid >> 5;
    int j0 = lane * 4, k0 = wid * 4;
    const float* ssB = g_ss + (size_t)b * Nn * 256;

    float qv4[8][4];
    #pragma unroll
    for (int h = 0; h < 8; h++)
        *(float4*)&qv4[h][0] = *(const float4*)&s_qk[h * 132 + j0];
    float4 base = *(const float4*)&s_base[j0];

    // per-ki: hMLP window + gelu + logits partials + 8-value reduction
    #pragma unroll
    for (int ki = 0; ki < 4; ki++) {
        int k = k0 + ki;
        int i0 = s_i0[k];
        float a0 = 0.0f, a1 = 0.0f, a2 = 0.0f, a3 = 0.0f;
        #pragma unroll
        for (int w = 0; w < WIN; w++) {
            float rb = s_rbf[k * 8 + w];
            float4 wv = *(const float4*)&s_wk1[(i0 + w) * 128 + j0];
            a0 = fmaf(rb, wv.x, a0);
            a1 = fmaf(rb, wv.y, a1);
            a2 = fmaf(rb, wv.z, a2);
            a3 = fmaf(rb, wv.w, a3);
        }
        float4 sv = *(const float4*)&ssB[(size_t)s_id[k] * 256 + j0];
        float g0 = gelu_fast(a0 + sv.x + base.x);
        float g1 = gelu_fast(a1 + sv.y + base.y);
        float g2 = gelu_fast(a2 + sv.z + base.z);
        float g3 = gelu_fast(a3 + sv.w + base.w);

        float p[8];
        #pragma unroll
        for (int h = 0; h < 8; h++)
            p[h] = g0*qv4[h][0] + g1*qv4[h][1] + g2*qv4[h][2] + g3*qv4[h][3];

        // stage A: sum within j-quads (xor 1, 2) - all 8 values
        #pragma unroll
        for (int h = 0; h < 8; h++) {
            p[h] += __shfl_xor_sync(0xffffffffu, p[h], 1);
            p[h] += __shfl_xor_sync(0xffffffffu, p[h], 2);
        }
        // stage B: reduce over 8 quads (xor 4, 8, 16), halving live values
        #pragma unroll
        for (int st = 0; st < 3; st++) {
            int s = 4 << st;
            int half = 4 >> st;
            #pragma unroll
            for (int i = 0; i < half; i++) {
                float send = (lane & s) ? p[i] : p[i + half];
                float recv = __shfl_xor_sync(0xffffffffu, send, s);
                p[i] = ((lane & s) ? p[i + half] : p[i]) + recv;
            }
        }
        if ((lane & 3) == 0) {
            int hf = ((lane & 4) ? 4 : 0) + ((lane & 8) ? 2 : 0) + ((lane & 16) ? 1 : 0);
            s_al[k * 8 + hf] = p[0] * 0.17677669529663687f;
        }
    }
    __syncthreads();

    // cutoff-weighted softmax over k, per head
    if (tid < Hh) {
        int h = tid;
        float mx = -3.4e38f;
        for (int k = 0; k < 32; k++) mx = fmaxf(mx, s_al[k * 8 + h]);
        float sum = 0.0f;
        for (int k = 0; k < 32; k++) {
            float w = s_cut[k] * exp_fast(s_al[k * 8 + h] - mx);
            s_al[k * 8 + h] = w;
            sum += w;
        }
        float invs = 1.0f / (sum + 1e-9f);
        for (int k = 0; k < 32; k++) s_al[k * 8 + h] *= invs;
    }
    __syncthreads();

    // asum[h][s] = sum_k alpha[k,h] * sh[k,s]
    if (tid < Hh * SHDc) {
        int h = tid / SHDc, s = tid % SHDc;
        float a = 0.0f;
        #pragma unroll 8
        for (int k = 0; k < 32; k++) a += s_al[k * 8 + h] * s_shl[k * SHDc + s];
        s_asum[tid] = a;
    }
    __syncthreads();

    // agg[d] = sum_k alpha[k,h(d)]*vn[src[k],d] + sum_s asum[h,s]*WvSh[s,d]
    {
        int d = tid;
        int h = d >> 5;
        const float* vnB = g_qv + (size_t)b * Nn * 512 + 256;
        float acc2 = 0.0f;
        #pragma unroll 8
        for (int k = 0; k < 32; k++)
            acc2 += s_al[k * 8 + h] * vnB[(size_t)s_id[k] * 512 + d];
        float proj = 0.0f;
        #pragma unroll
        for (int s = 0; s < SHDc; s++) proj += s_asum[h * SHDc + s] * s_wvsh[s * 256 + d];
        g_agg[(size_t)m * Dd + d] = acc2 + proj;
    }
}

// ---------------- final projection ----------------
__global__ void final_kernel(const float* __restrict__ Wo_out, float* __restrict__ out) {
    int gid = blockIdx.x * blockDim.x + threadIdx.x;
    if (gid >= Mm * 3) return;
    int m = gid / 3, c = gid % 3;
    const float* a = g_agg + (size_t)m * Dd;
    float acc = 0.0f;
    #pragma unroll 8
    for (int j = 0; j < Dd; j++) acc += a[j] * Wo_out[j * 3 + c];
    out[gid] = acc;
}

// ---------------- host orchestration ----------------
extern "C" void kernel_launch(void* const* d_in, const int* in_sizes, int n_in,
                              void* d_out, int out_size) {
    const float* x       = (const float*)d_in[0];
    const float* y       = (const float*)d_in[1];
    const float* t       = (const float*)d_in[2];
    const float* W_embed = (const float*)d_in[3];
    const float* Wk1     = (const float*)d_in[4];
    const float* bk1     = (const float*)d_in[5];
    const float* Wk2     = (const float*)d_in[6];
    const float* Wq      = (const float*)d_in[7];
    const float* Wv      = (const float*)d_in[8];
    const float* Wo      = (const float*)d_in[9];
    const float* Wo_out  = (const float*)d_in[10];
    float* out = (float*)d_out;

    float *p_node, *p_qv, *p_ss, *p_agg;
    uint32_t *p_wcat1, *p_wcat2, *p_wcat3;
    cudaGetSymbolAddress((void**)&p_node,  g_node);
    cudaGetSymbolAddress((void**)&p_qv,    g_qv);
    cudaGetSymbolAddress((void**)&p_ss,    g_ss);
    cudaGetSymbolAddress((void**)&p_agg,   g_agg);
    cudaGetSymbolAddress((void**)&p_wcat1, g_wcat1);
    cudaGetSymbolAddress((void**)&p_wcat2, g_wcat2);
    cudaGetSymbolAddress((void**)&p_wcat3, g_wcat3);

    const int PACKN = Lc * 256 * 512 + Lc * 128 * 256 + 3 * 256 * 256;

    // ncu captures the 4th launch: knn this round.
    embed_kernel<<<Mm, Dd>>>(y, t, W_embed);                                   // 1
    pack_kernel<<<(PACKN + 255) / 256, 256>>>(Wq, Wv, Wk1, Wo);                // 2
    tpart_kernel<<<Lc * Bb, HIDc>>>(t, Wk1, bk1);                              // 3
    knn_kernel<<<dim3(Nn / 8, Bb), 256>>>(x);                                  // 4 <- profiled
    geom_kernel<<<(Mm * Kk + 255) / 256, 256>>>(x);                            // 5

    for (int l = 0; l < Lc; l++) {
        gemm_tc<<<dim3(Mm / 128, 512 / 128), 256>>>(
            p_node, Dd, p_wcat1 + (size_t)l * 256 * 512, 512,
            p_qv, 512, 256, nullptr, 0);
        gemm_tc<<<dim3(Mm / 128, 256 / 128), 256>>>(
            p_node, Dd, p_wcat2 + (size_t)l * 128 * 256, 256,
            p_ss, 256, 128, nullptr, 0);
        qk_tc<<<dim3(Mm / 128, Hh), 256>>>(Wk2, l);
        edge_kernel<<<Mm, 256>>>(Wk1, Wv, l);

        if (l < Lc - 1) {
            gemm_tc<<<dim3(Mm / 128, 256 / 128), 256>>>(
                p_agg, Dd, p_wcat3 + (size_t)l * 256 * 256, 256,
                p_node, Dd, 256, p_node, 1);
        } else {
            final_kernel<<<(Mm * 3 + 255) / 256, 256>>>(Wo_out, out);
        }
    }
}

// round 15
// speedup vs baseline: 1.1457x; 1.1457x over previous
#include <cuda_runtime.h>
#include <math.h>
#include <stdint.h>

// ---------------- problem dims ----------------
#define Bb    8
#define Nn    1024
#define Kk    32
#define Dd    256
#define Hh    8
#define DHh   32
#define TDIMc 16
#define NBc   32
#define HIDc  128
#define Lc    4
#define NSc   128
#define SHDc  9
#define EINc  304
#define Mm    (Bb*Nn)
#define WIN   8

// ---------------- scratch (device globals; no allocs allowed) ----------------
__device__ int   g_src [Mm*Kk];
__device__ float g_cutb[Mm*Kk];
__device__ int   g_win [Mm*Kk];
__device__ float g_sh  [Mm*Kk*SHDc];
__device__ float g_rbf [Mm*Kk*NBc];     // full 32-wide rbf*cut (R10 layout)
__device__ float g_node[Mm*Dd];
__device__ float g_qv  [Mm*512];
__device__ float g_ss  [Mm*256];
__device__ float g_agg [Mm*Dd];
__device__ float g_qk  [Mm*Hh*HIDc];
__device__ float g_tpart[Lc*Bb*HIDc];
__device__ uint32_t g_wcat1[Lc*256*512]; // tf32 [l][k][ Wq | Wv_top ]
__device__ uint32_t g_wcat2[Lc*128*256]; // tf32 [l][k][ Wk1_src | Wk1_dst ]
__device__ uint32_t g_wcat3[3*256*256];  // tf32 [l][k][ Wo ]

// ---------------- FFMA-only fast math ----------------
__device__ __forceinline__ float fast_rcp(float q) {
    float r = __int_as_float(0x7EF311C3 - __float_as_int(q));
    r = r * (2.0f - q * r);
    r = r * (2.0f - q * r);
    r = r * (2.0f - q * r);
    return r;
}
__device__ __forceinline__ float tanh_fast(float x) {
    x = fminf(fmaxf(x, -7.90531110591f), 7.90531110591f);
    float x2 = x * x;
    float p = fmaf(x2, -2.76076847742355e-16f, 2.00018790482477e-13f);
    p = fmaf(x2, p, -8.60467152213735e-11f);
    p = fmaf(x2, p,  5.12229709037114e-08f);
    p = fmaf(x2, p,  1.48572235717979e-05f);
    p = fmaf(x2, p,  6.37261928875436e-04f);
    p = fmaf(x2, p,  4.89352455891786e-03f);
    p = p * x;
    float q = fmaf(x2, 1.19825839466702e-06f, 1.18534705686654e-04f);
    q = fmaf(x2, q, 2.26843463243900e-03f);
    q = fmaf(x2, q, 4.89352518554385e-03f);
    return p * fast_rcp(q);
}
__device__ __forceinline__ float gelu_fast(float v) {
    float c = v * fmaf(v * v, 0.0356774081363f, 0.7978845608028654f);
    return 0.5f * v * (1.0f + tanh_fast(c));
}
__device__ __forceinline__ float exp_fast(float x) {
    x = fmaxf(x, -80.0f);
    float y = x * 1.4426950408889634f;
    float n = floorf(y);
    float f = y - n;
    float p = 1.5252733804059838e-5f;
    p = fmaf(p, f, 1.5403530393381606e-4f);
    p = fmaf(p, f, 1.3333558146428443e-3f);
    p = fmaf(p, f, 9.618129107628477e-3f);
    p = fmaf(p, f, 5.550410866482158e-2f);
    p = fmaf(p, f, 2.402265069591007e-1f);
    p = fmaf(p, f, 6.931471805599453e-1f);
    p = fmaf(p, f, 1.0f);
    return p * __int_as_float(((int)n + 127) << 23);
}
__device__ __forceinline__ uint32_t f2tf32(float f) {
    uint32_t u;
    asm("cvt.rna.tf32.f32 %0, %1;" : "=r"(u) : "f"(f));
    return u;
}
__device__ __forceinline__ void mma_tf32(float c[4], uint32_t a0, uint32_t a1,
                                         uint32_t a2, uint32_t a3,
                                         uint32_t b0, uint32_t b1) {
    asm volatile(
        "mma.sync.aligned.m16n8k8.row.col.f32.tf32.tf32.f32 "
        "{%0,%1,%2,%3}, {%4,%5,%6,%7}, {%8,%9}, {%0,%1,%2,%3};"
        : "+f"(c[0]), "+f"(c[1]), "+f"(c[2]), "+f"(c[3])
        : "r"(a0), "r"(a1), "r"(a2), "r"(a3), "r"(b0), "r"(b1));
}

// ---------------- warp-collective kNN: cheap insertion (max + ballot) ----------------
__global__ void knn_kernel(const float* __restrict__ x) {
    __shared__ float px[Nn], py[Nn], pz[Nn];
    int b = blockIdx.y;
    const float* xb = x + (size_t)b * Nn * 3;
    for (int i = threadIdx.x; i < Nn; i += blockDim.x) {
        px[i] = xb[i*3+0]; py[i] = xb[i*3+1]; pz[i] = xb[i*3+2];
    }
    __syncthreads();
    int warp = threadIdx.x >> 5, lane = threadIdx.x & 31;
    int n = blockIdx.x * 8 + warp;
    float qx = px[n], qy = py[n], qz = pz[n];

    float dx = qx - px[lane], dy = qy - py[lane], dz = qz - pz[lane];
    float best_d = dx*dx + dy*dy + dz*dz;
    int   best_i = lane;
    float thr = best_d;
    #pragma unroll
    for (int off = 16; off; off >>= 1) thr = fmaxf(thr, __shfl_xor_sync(~0u, thr, off));
    int thr_lane = __ffs(__ballot_sync(~0u, best_d == thr)) - 1;

    for (int j0 = 32; j0 < Nn; j0 += 32) {
        int j = j0 + lane;
        dx = qx - px[j]; dy = qy - py[j]; dz = qz - pz[j];
        float d2 = dx*dx + dy*dy + dz*dz;
        unsigned mask = __ballot_sync(~0u, d2 < thr);
        while (mask) {
            int src = __ffs(mask) - 1; mask &= mask - 1;
            float cd = __shfl_sync(~0u, d2, src);
            if (cd < thr) {
                if (lane == thr_lane) { best_d = cd; best_i = j0 + src; }
                float m = best_d;
                #pragma unroll
                for (int off = 16; off; off >>= 1)
                    m = fmaxf(m, __shfl_xor_sync(~0u, m, off));
                thr = m;
                thr_lane = __ffs(__ballot_sync(~0u, best_d == m)) - 1;
            }
        }
    }
    g_src[(b * Nn + n) * Kk + lane] = best_i;
}

// ---------------- per-edge geometry (R10: full 32 rbf + window index) ----------------
__global__ void geom_kernel(const float* __restrict__ x) {
    int gid = blockIdx.x * blockDim.x + threadIdx.x;
    if (gid >= Mm * Kk) return;
    int m = gid / Kk;
    int b = m / Nn, n = m % Nn;
    int s = g_src[gid];
    const float* xb = x + (size_t)b * Nn * 3;
    float vx = xb[n*3+0] - xb[s*3+0];
    float vy = xb[n*3+1] - xb[s*3+1];
    float vz = xb[n*3+2] - xb[s*3+2];
    float r = sqrtf(vx*vx + vy*vy + vz*vz);
    float xc = 10.0f - 5.0f * r;
    float cut = (xc > 0.0f) ? 1.4f * exp_fast(-fast_rcp(xc)) : 0.0f;
    g_cutb[gid] = cut;
    float inv = 1.0f / fmaxf(r, 1e-9f);
    float ux = vx * inv, uy = vy * inv, uz = vz * inv;
    const float s3 = 1.7320508075688772f;
    const float s15 = 3.872983346207417f;
    const float h5 = 1.118033988749895f;
    const float h15 = 1.9364916731037085f;
    float* sh = g_sh + (size_t)gid * SHDc;
    sh[0] = 1.0f;
    sh[1] = s3 * ux; sh[2] = s3 * uy; sh[3] = s3 * uz;
    sh[4] = s15 * ux * uy;
    sh[5] = s15 * uy * uz;
    sh[6] = h5 * (3.0f * uz * uz - 1.0f);
    sh[7] = s15 * ux * uz;
    sh[8] = h15 * (ux * ux - uy * uy);
    const float ISTEP = 15.5f;
    const float RBFC  = 5.656854249492381f * 0.95f / 1.12f;
    float base = r * ISTEP;
    int i0 = (int)floorf(base) - 3;
    i0 = max(0, min(24, i0));
    g_win[gid] = i0;
    float rb[NBc];
    #pragma unroll
    for (int ii = 0; ii < NBc; ii++) {
        float d = base - (float)ii;
        rb[ii] = exp_fast(-d * d) * RBFC * cut;
    }
    float4* dst = (float4*)(g_rbf + (size_t)gid * NBc);
    #pragma unroll
    for (int u = 0; u < 8; u++)
        dst[u] = make_float4(rb[u*4], rb[u*4+1], rb[u*4+2], rb[u*4+3]);
}

// ---------------- node embedding ----------------
__global__ void embed_kernel(const float* __restrict__ y, const float* __restrict__ t,
                             const float* __restrict__ W_embed) {
    __shared__ float in[3 + TDIMc];
    int m = blockIdx.x;
    int b = m / Nn;
    int tid = threadIdx.x;
    if (tid < 3) in[tid] = y[(size_t)m * 3 + tid];
    else if (tid < 3 + TDIMc) in[tid] = t[b * TDIMc + (tid - 3)];
    __syncthreads();
    float acc = 0.0f;
    #pragma unroll
    for (int i = 0; i < 3 + TDIMc; i++) acc += in[i] * W_embed[i * Dd + tid];
    g_node[(size_t)m * Dd + tid] = acc;
}

// ---------------- tpart ----------------
__global__ void tpart_kernel(const float* __restrict__ t, const float* __restrict__ Wk1,
                             const float* __restrict__ bk1) {
    int l = blockIdx.x / Bb, b = blockIdx.x % Bb;
    int j = threadIdx.x;
    float acc = bk1[l * HIDc + j];
    #pragma unroll
    for (int i = 0; i < TDIMc; i++)
        acc += t[b * TDIMc + i] * Wk1[((size_t)l * EINc + 32 + i) * HIDc + j];
    g_tpart[(l * Bb + b) * HIDc + j] = acc;
}

// ---------------- pack weights -> tf32 ----------------
__global__ void pack_kernel(const float* __restrict__ Wq, const float* __restrict__ Wv,
                            const float* __restrict__ Wk1, const float* __restrict__ Wo) {
    int i = blockIdx.x * 256 + threadIdx.x;
    const int SZ1 = Lc * 256 * 512;
    const int SZ2 = Lc * 128 * 256;
    if (i < SZ1) {
        int l = i / (256 * 512);
        int r = (i >> 9) & 255;
        int n = i & 511;
        float v = (n < 256) ? Wq[((size_t)l * 256 + r) * 256 + n]
                            : Wv[((size_t)l * (Dd + SHDc) + r) * 256 + (n - 256)];
        g_wcat1[i] = f2tf32(v);
    } else if (i < SZ1 + SZ2) {
        int j = i - SZ1;
        int l = j / (128 * 256);
        int r = (j >> 8) & 127;
        int n = j & 255;
        int row = (n < 128) ? (48 + r) : (176 + r);
        g_wcat2[j] = f2tf32(Wk1[((size_t)l * EINc + row) * HIDc + (n & 127)]);
    } else {
        int j = i - SZ1 - SZ2;
        if (j < 3 * 256 * 256) g_wcat3[j] = f2tf32(Wo[j]);
    }
}

// ---------------- TF32 TC GEMM, register-prefetch pipelined ----------------
__global__ void __launch_bounds__(256, 2)
gemm_tc(const float* __restrict__ A, int lda,
        const uint32_t* __restrict__ W, int ldw,
        float* __restrict__ C, int ldc, int Kd,
        const float* __restrict__ resid, int actmode) {
    __shared__ uint32_t sA[32 * 132];
    __shared__ uint32_t sB[32 * 132];
    int m0 = blockIdx.x * 128, n0 = blockIdx.y * 128;
    int tid = threadIdx.x, lane = tid & 31, wid = tid >> 5;
    int wm = (wid & 1) * 64, wn = (wid >> 1) * 32;
    int gp = lane >> 2, tg = lane & 3;

    int amm[4], akq[4], bkk[4], bnq[4];
    #pragma unroll
    for (int u = 0; u < 4; u++) {
        int id = tid + u * 256;
        amm[u] = id >> 3; akq[u] = (id & 7) * 4;
        bkk[u] = id >> 5; bnq[u] = (id & 31) * 4;
    }

    float c[4][4][4];
    #pragma unroll
    for (int i = 0; i < 4; i++)
        #pragma unroll
        for (int j = 0; j < 4; j++)
            #pragma unroll
            for (int r = 0; r < 4; r++) c[i][j][r] = 0.0f;

    float4 pa[4];
    uint4  pb[4];
    #pragma unroll
    for (int u = 0; u < 4; u++) {
        pa[u] = *(const float4*)&A[(size_t)(m0 + amm[u]) * lda + akq[u]];
        pb[u] = *(const uint4*)&W[(size_t)bkk[u] * ldw + n0 + bnq[u]];
    }

    for (int kt = 0; kt < Kd; kt += 32) {
        #pragma unroll
        for (int u = 0; u < 4; u++) {
            sA[(akq[u] + 0) * 132 + amm[u]] = f2tf32(pa[u].x);
            sA[(akq[u] + 1) * 132 + amm[u]] = f2tf32(pa[u].y);
            sA[(akq[u] + 2) * 132 + amm[u]] = f2tf32(pa[u].z);
            sA[(akq[u] + 3) * 132 + amm[u]] = f2tf32(pa[u].w);
            *(uint4*)&sB[bkk[u] * 132 + bnq[u]] = pb[u];
        }
        __syncthreads();
        if (kt + 32 < Kd) {
            #pragma unroll
            for (int u = 0; u < 4; u++) {
                pa[u] = *(const float4*)&A[(size_t)(m0 + amm[u]) * lda + kt + 32 + akq[u]];
                pb[u] = *(const uint4*)&W[(size_t)(kt + 32 + bkk[u]) * ldw + n0 + bnq[u]];
            }
        }
        #pragma unroll
        for (int ka = 0; ka < 4; ka++) {
            int kb = ka * 8;
            uint32_t bf[4][2];
            #pragma unroll
            for (int na = 0; na < 4; na++) {
                bf[na][0] = sB[(kb + tg) * 132 + wn + na * 8 + gp];
                bf[na][1] = sB[(kb + tg + 4) * 132 + wn + na * 8 + gp];
            }
            #pragma unroll
            for (int ma = 0; ma < 4; ma++) {
                int mb = wm + ma * 16 + gp;
                uint32_t a0 = sA[(kb + tg) * 132 + mb];
                uint32_t a1 = sA[(kb + tg) * 132 + mb + 8];
                uint32_t a2 = sA[(kb + tg + 4) * 132 + mb];
                uint32_t a3 = sA[(kb + tg + 4) * 132 + mb + 8];
                #pragma unroll
                for (int na = 0; na < 4; na++)
                    mma_tf32(c[ma][na], a0, a1, a2, a3, bf[na][0], bf[na][1]);
            }
        }
        __syncthreads();
    }

    #pragma unroll
    for (int ma = 0; ma < 4; ma++) {
        int row = m0 + wm + ma * 16 + gp;
        #pragma unroll
        for (int na = 0; na < 4; na++) {
            int col = n0 + wn + na * 8 + 2 * tg;
            #pragma unroll
            for (int half = 0; half < 2; half++) {
                int rr = row + half * 8;
                float v0 = c[ma][na][half * 2 + 0];
                float v1 = c[ma][na][half * 2 + 1];
                if (actmode == 1) {
                    float2 rs = *(const float2*)&resid[(size_t)rr * ldc + col];
                    v0 += rs.x; v1 += rs.y;
                    if (col < 64)       { v0 = gelu_fast(v0); v1 = gelu_fast(v1); }
                    else if (col < 128) { v0 = tanh_fast(v0); v1 = tanh_fast(v1); }
                }
                float2 o = make_float2(v0, v1);
                *(float2*)&C[(size_t)rr * ldc + col] = o;
            }
        }
    }
}

// ---------------- qk on tensor cores ----------------
__global__ void qk_tc(const float* __restrict__ Wk2, int l) {
    __shared__ uint32_t sA[32 * 132];
    __shared__ uint32_t sB[32 * 132];
    int m0 = blockIdx.x * 128;
    int h  = blockIdx.y;
    int tid = threadIdx.x, lane = tid & 31, wid = tid >> 5;
    int wm = (wid & 1) * 64, wn = (wid >> 1) * 32;
    int gp = lane >> 2, tg = lane & 3;
    const float* W = Wk2 + (size_t)l * HIDc * Dd;

    #pragma unroll
    for (int u = 0; u < 4; u++) {
        int id = tid + u * 256;
        int mm = id >> 3, kq = (id & 7) * 4;
        float4 v = *(const float4*)&g_qv[(size_t)(m0 + mm) * 512 + h * 32 + kq];
        sA[(kq + 0) * 132 + mm] = f2tf32(v.x);
        sA[(kq + 1) * 132 + mm] = f2tf32(v.y);
        sA[(kq + 2) * 132 + mm] = f2tf32(v.z);
        sA[(kq + 3) * 132 + mm] = f2tf32(v.w);
    }
    #pragma unroll
    for (int u = 0; u < 4; u++) {
        int id = tid + u * 256;
        int j = id >> 3, kq = (id & 7) * 4;
        float4 v = *(const float4*)&W[(size_t)j * 256 + h * 32 + kq];
        sB[(kq + 0) * 132 + j] = f2tf32(v.x);
        sB[(kq + 1) * 132 + j] = f2tf32(v.y);
        sB[(kq + 2) * 132 + j] = f2tf32(v.z);
        sB[(kq + 3) * 132 + j] = f2tf32(v.w);
    }
    __syncthreads();

    float c[4][4][4];
    #pragma unroll
    for (int i = 0; i < 4; i++)
        #pragma unroll
        for (int j = 0; j < 4; j++)
            #pragma unroll
            for (int r = 0; r < 4; r++) c[i][j][r] = 0.0f;

    #pragma unroll
    for (int ka = 0; ka < 4; ka++) {
        int kb = ka * 8;
        uint32_t bf[4][2];
        #pragma unroll
        for (int na = 0; na < 4; na++) {
            bf[na][0] = sB[(kb + tg) * 132 + wn + na * 8 + gp];
            bf[na][1] = sB[(kb + tg + 4) * 132 + wn + na * 8 + gp];
        }
        #pragma unroll
        for (int ma = 0; ma < 4; ma++) {
            int mb = wm + ma * 16 + gp;
            uint32_t a0 = sA[(kb + tg) * 132 + mb];
            uint32_t a1 = sA[(kb + tg) * 132 + mb + 8];
            uint32_t a2 = sA[(kb + tg + 4) * 132 + mb];
            uint32_t a3 = sA[(kb + tg + 4) * 132 + mb + 8];
            #pragma unroll
            for (int na = 0; na < 4; na++)
                mma_tf32(c[ma][na], a0, a1, a2, a3, bf[na][0], bf[na][1]);
        }
    }

    #pragma unroll
    for (int ma = 0; ma < 4; ma++) {
        int row = m0 + wm + ma * 16 + gp;
        #pragma unroll
        for (int na = 0; na < 4; na++) {
            int col = wn + na * 8 + 2 * tg;
            #pragma unroll
            for (int half = 0; half < 2; half++) {
                int rr = row + half * 8;
                float2 o = make_float2(c[ma][na][half * 2 + 0], c[ma][na][half * 2 + 1]);
                *(float2*)&g_qk[(size_t)rr * 1024 + h * 128 + col] = o;
            }
        }
    }
}

// ---------------- fused edge kernel (R10-exact dataflow) ----------------
__global__ void edge_kernel(const float* __restrict__ Wk1, const float* __restrict__ Wv,
                            int l) {
    __shared__ float s_wk1[32 * 128];   // [ii][j]
    __shared__ float s_rbf[32 * 36];    // [k][ii] natural layout
    __shared__ float s_qk [8 * 132];    // [h][j]
    __shared__ float s_al [32 * 8];     // [k][h]
    __shared__ float s_shl[32 * 9];     // [k][s]
    __shared__ float s_wvsh[9 * 256];   // [s][d]
    __shared__ float s_asum[Hh * SHDc]; // [h][s]
    __shared__ float s_base[128];
    __shared__ float s_cut[32];
    __shared__ int   s_id[32];
    __shared__ int   s_i0[32];

    int m = blockIdx.x;
    int b = m >> 10;
    int tid = threadIdx.x;
    const float* Wk1l = Wk1 + (size_t)l * EINc * HIDc;
    const float* WvSh = Wv + ((size_t)l * (Dd + SHDc) + Dd) * Dd;
    const float* tpl  = g_tpart + (l * Bb + b) * HIDc;

    if (tid < 32) {
        s_id[tid]  = g_src [m * 32 + tid];
        s_cut[tid] = g_cutb[m * 32 + tid];
        s_i0[tid]  = g_win [m * 32 + tid];
    }
    if (tid < 128) s_base[tid] = g_ss[(size_t)m * 256 + 128 + tid] + tpl[tid];
    for (int i = tid; i < 1024; i += 256) {
        int h = i >> 7, j = i & 127;
        s_qk[h * 132 + j] = g_qk[(size_t)m * 1024 + i];
    }
    for (int i = tid; i < 32 * SHDc; i += 256) s_shl[i] = g_sh[(size_t)m * 32 * SHDc + i];
    {   // rbf load, natural [k][ii] layout, stride 36
        float4 v = *(const float4*)&g_rbf[(size_t)m * 1024 + tid * 4];
        int k = tid >> 3, ii0 = (tid & 7) * 4;
        *(float4*)&s_rbf[k * 36 + ii0] = v;
    }
    #pragma unroll
    for (int u = 0; u < 4; u++) {
        int idx = (tid + u * 256) * 4;
        *(float4*)&s_wk1[idx] = *(const float4*)&Wk1l[idx];
    }
    #pragma unroll
    for (int u = 0; u < 3; u++) {
        int i = tid + u * 256;
        if (i < 576) *(float4*)&s_wvsh[i * 4] = *(const float4*)&WvSh[i * 4];
    }
    __syncthreads();

    int lane = tid & 31, wid = tid >> 5;
    int j0 = lane * 4, k0 = wid * 4;
    float acc[4][4];
    #pragma unroll
    for (int ki = 0; ki < 4; ki++) {
        int k = k0 + ki;
        int i0 = s_i0[k];
        float a0 = 0.0f, a1 = 0.0f, a2 = 0.0f, a3 = 0.0f;
        #pragma unroll
        for (int w = 0; w < WIN; w++) {
            int ii = i0 + w;
            float rb = s_rbf[k * 36 + ii];
            float4 wv = *(const float4*)&s_wk1[ii * 128 + j0];
            a0 = fmaf(rb, wv.x, a0);
            a1 = fmaf(rb, wv.y, a1);
            a2 = fmaf(rb, wv.z, a2);
            a3 = fmaf(rb, wv.w, a3);
        }
        acc[ki][0] = a0; acc[ki][1] = a1; acc[ki][2] = a2; acc[ki][3] = a3;
    }
    float qv4[8][4];
    #pragma unroll
    for (int h = 0; h < 8; h++)
        *(float4*)&qv4[h][0] = *(const float4*)&s_qk[h * 132 + j0];

    const float* ssB = g_ss + (size_t)b * Nn * 256;
    float4 base = *(const float4*)&s_base[j0];
    float v[32];
    #pragma unroll
    for (int ki = 0; ki < 4; ki++) {
        int k = k0 + ki;
        float4 sv = *(const float4*)&ssB[(size_t)s_id[k] * 256 + j0];
        float gl[4];
        gl[0] = gelu_fast(acc[ki][0] + sv.x + base.x);
        gl[1] = gelu_fast(acc[ki][1] + sv.y + base.y);
        gl[2] = gelu_fast(acc[ki][2] + sv.z + base.z);
        gl[3] = gelu_fast(acc[ki][3] + sv.w + base.w);
        #pragma unroll
        for (int h = 0; h < 8; h++) {
            float s = gl[0]*qv4[h][0] + gl[1]*qv4[h][1] + gl[2]*qv4[h][2] + gl[3]*qv4[h][3];
            v[ki * 8 + h] = s;
        }
    }
    #pragma unroll
    for (int s = 16; s >= 1; s >>= 1) {
        #pragma unroll
        for (int i = 0; i < s; i++) {
            float send = (lane & s) ? v[i] : v[i + s];
            float recv = __shfl_xor_sync(0xffffffffu, send, s);
            v[i] = ((lane & s) ? v[i + s] : v[i]) + recv;
        }
    }
    s_al[(k0 + (lane >> 3)) * 8 + (lane & 7)] = v[0] * 0.17677669529663687f;
    __syncthreads();

    if (tid < Hh) {
        int h = tid;
        float mx = -3.4e38f;
        for (int k = 0; k < 32; k++) mx = fmaxf(mx, s_al[k * 8 + h]);
        float sum = 0.0f;
        for (int k = 0; k < 32; k++) {
            float w = s_cut[k] * exp_fast(s_al[k * 8 + h] - mx);
            s_al[k * 8 + h] = w;
            sum += w;
        }
        float invs = 1.0f / (sum + 1e-9f);
        for (int k = 0; k < 32; k++) s_al[k * 8 + h] *= invs;
    }
    __syncthreads();

    if (tid < Hh * SHDc) {
        int h = tid / SHDc, s = tid % SHDc;
        float a = 0.0f;
        #pragma unroll 8
        for (int k = 0; k < 32; k++) a += s_al[k * 8 + h] * s_shl[k * SHDc + s];
        s_asum[tid] = a;
    }
    __syncthreads();

    {
        int d = tid;
        int h = d >> 5;
        const float* vnB = g_qv + (size_t)b * Nn * 512 + 256;
        float acc2 = 0.0f;
        #pragma unroll 8
        for (int k = 0; k < 32; k++)
            acc2 += s_al[k * 8 + h] * vnB[(size_t)s_id[k] * 512 + d];
        float proj = 0.0f;
        #pragma unroll
        for (int s = 0; s < SHDc; s++) proj += s_asum[h * SHDc + s] * s_wvsh[s * 256 + d];
        g_agg[(size_t)m * Dd + d] = acc2 + proj;
    }
}

// ---------------- final projection ----------------
__global__ void final_kernel(const float* __restrict__ Wo_out, float* __restrict__ out) {
    int gid = blockIdx.x * blockDim.x + threadIdx.x;
    if (gid >= Mm * 3) return;
    int m = gid / 3, c = gid % 3;
    const float* a = g_agg + (size_t)m * Dd;
    float acc = 0.0f;
    #pragma unroll 8
    for (int j = 0; j < Dd; j++) acc += a[j] * Wo_out[j * 3 + c];
    out[gid] = acc;
}

// ---------------- host orchestration ----------------
extern "C" void kernel_launch(void* const* d_in, const int* in_sizes, int n_in,
                              void* d_out, int out_size) {
    const float* x       = (const float*)d_in[0];
    const float* y       = (const float*)d_in[1];
    const float* t       = (const float*)d_in[2];
    const float* W_embed = (const float*)d_in[3];
    const float* Wk1     = (const float*)d_in[4];
    const float* bk1     = (const float*)d_in[5];
    const float* Wk2     = (const float*)d_in[6];
    const float* Wq      = (const float*)d_in[7];
    const float* Wv      = (const float*)d_in[8];
    const float* Wo      = (const float*)d_in[9];
    const float* Wo_out  = (const float*)d_in[10];
    float* out = (float*)d_out;

    float *p_node, *p_qv, *p_ss, *p_agg;
    uint32_t *p_wcat1, *p_wcat2, *p_wcat3;
    cudaGetSymbolAddress((void**)&p_node,  g_node);
    cudaGetSymbolAddress((void**)&p_qv,    g_qv);
    cudaGetSymbolAddress((void**)&p_ss,    g_ss);
    cudaGetSymbolAddress((void**)&p_agg,   g_agg);
    cudaGetSymbolAddress((void**)&p_wcat1, g_wcat1);
    cudaGetSymbolAddress((void**)&p_wcat2, g_wcat2);
    cudaGetSymbolAddress((void**)&p_wcat3, g_wcat3);

    const int PACKN = Lc * 256 * 512 + Lc * 128 * 256 + 3 * 256 * 256;

    // ncu captures the 4th launch: knn (re-measure the insertion fix).
    embed_kernel<<<Mm, Dd>>>(y, t, W_embed);                                   // 1
    pack_kernel<<<(PACKN + 255) / 256, 256>>>(Wq, Wv, Wk1, Wo);                // 2
    tpart_kernel<<<Lc * Bb, HIDc>>>(t, Wk1, bk1);                              // 3
    knn_kernel<<<dim3(Nn / 8, Bb), 256>>>(x);                                  // 4 <- profiled
    geom_kernel<<<(Mm * Kk + 255) / 256, 256>>>(x);                            // 5

    for (int l = 0; l < Lc; l++) {
        gemm_tc<<<dim3(Mm / 128, 512 / 128), 256>>>(
            p_node, Dd, p_wcat1 + (size_t)l * 256 * 512, 512,
            p_qv, 512, 256, nullptr, 0);
        gemm_tc<<<dim3(Mm / 128, 256 / 128), 256>>>(
            p_node, Dd, p_wcat2 + (size_t)l * 128 * 256, 256,
            p_ss, 256, 128, nullptr, 0);
        qk_tc<<<dim3(Mm / 128, Hh), 256>>>(Wk2, l);
        edge_kernel<<<Mm, 256>>>(Wk1, Wv, l);

        if (l < Lc - 1) {
            gemm_tc<<<dim3(Mm / 128, 256 / 128), 256>>>(
                p_agg, Dd, p_wcat3 + (size_t)l * 256 * 256, 256,
                p_node, Dd, 256, p_node, 1);
        } else {
            final_kernel<<<(Mm * 3 + 255) / 256, 256>>>(Wo_out, out);
        }
    }
}

// round 16
// speedup vs baseline: 1.1579x; 1.0107x over previous
#include <cuda_runtime.h>
#include <math.h>
#include <stdint.h>

// ---------------- problem dims ----------------
#define Bb    8
#define Nn    1024
#define Kk    32
#define Dd    256
#define Hh    8
#define DHh   32
#define TDIMc 16
#define NBc   32
#define HIDc  128
#define Lc    4
#define NSc   128
#define SHDc  9
#define EINc  304
#define Mm    (Bb*Nn)
#define WIN   8

// ---------------- scratch (device globals; no allocs allowed) ----------------
__device__ int   g_src [Mm*Kk];
__device__ float g_cutb[Mm*Kk];
__device__ int   g_win [Mm*Kk];
__device__ float g_sh  [Mm*Kk*SHDc];
__device__ float g_rbf [Mm*Kk*NBc];
__device__ float g_node[Mm*Dd];
__device__ float g_qv  [Mm*512];
__device__ float g_ss  [Mm*256];
__device__ float g_agg [Mm*Dd];
__device__ float g_qk  [Mm*Hh*HIDc];
__device__ float g_tpart[Lc*Bb*HIDc];
__device__ uint32_t g_wcat1[Lc*256*512]; // tf32 [l][k][ Wq | Wv_top ]
__device__ uint32_t g_wcat2[Lc*128*256]; // tf32 [l][k][ Wk1_src | Wk1_dst ]
__device__ uint32_t g_wcat3[3*256*256];  // tf32 [l][k][ Wo ]

// ---------------- FFMA-only fast math ----------------
__device__ __forceinline__ float fast_rcp(float q) {
    float r = __int_as_float(0x7EF311C3 - __float_as_int(q));
    r = r * (2.0f - q * r);
    r = r * (2.0f - q * r);
    r = r * (2.0f - q * r);
    return r;
}
__device__ __forceinline__ float tanh_fast(float x) {
    x = fminf(fmaxf(x, -7.90531110591f), 7.90531110591f);
    float x2 = x * x;
    float p = fmaf(x2, -2.76076847742355e-16f, 2.00018790482477e-13f);
    p = fmaf(x2, p, -8.60467152213735e-11f);
    p = fmaf(x2, p,  5.12229709037114e-08f);
    p = fmaf(x2, p,  1.48572235717979e-05f);
    p = fmaf(x2, p,  6.37261928875436e-04f);
    p = fmaf(x2, p,  4.89352455891786e-03f);
    p = p * x;
    float q = fmaf(x2, 1.19825839466702e-06f, 1.18534705686654e-04f);
    q = fmaf(x2, q, 2.26843463243900e-03f);
    q = fmaf(x2, q, 4.89352518554385e-03f);
    return p * fast_rcp(q);
}
__device__ __forceinline__ float gelu_fast(float v) {
    float c = v * fmaf(v * v, 0.0356774081363f, 0.7978845608028654f);
    return 0.5f * v * (1.0f + tanh_fast(c));
}
__device__ __forceinline__ float exp_fast(float x) {
    x = fmaxf(x, -80.0f);
    float y = x * 1.4426950408889634f;
    float n = floorf(y);
    float f = y - n;
    float p = 1.5252733804059838e-5f;
    p = fmaf(p, f, 1.5403530393381606e-4f);
    p = fmaf(p, f, 1.3333558146428443e-3f);
    p = fmaf(p, f, 9.618129107628477e-3f);
    p = fmaf(p, f, 5.550410866482158e-2f);
    p = fmaf(p, f, 2.402265069591007e-1f);
    p = fmaf(p, f, 6.931471805599453e-1f);
    p = fmaf(p, f, 1.0f);
    return p * __int_as_float(((int)n + 127) << 23);
}
__device__ __forceinline__ uint32_t f2tf32(float f) {
    uint32_t u;
    asm("cvt.rna.tf32.f32 %0, %1;" : "=r"(u) : "f"(f));
    return u;
}
__device__ __forceinline__ void mma_tf32(float c[4], uint32_t a0, uint32_t a1,
                                         uint32_t a2, uint32_t a3,
                                         uint32_t b0, uint32_t b1) {
    asm volatile(
        "mma.sync.aligned.m16n8k8.row.col.f32.tf32.tf32.f32 "
        "{%0,%1,%2,%3}, {%4,%5,%6,%7}, {%8,%9}, {%0,%1,%2,%3};"
        : "+f"(c[0]), "+f"(c[1]), "+f"(c[2]), "+f"(c[3])
        : "r"(a0), "r"(a1), "r"(a2), "r"(a3), "r"(b0), "r"(b1));
}

// ---------------- warp-collective kNN: cheap insertion (max + ballot) ----------------
__global__ void knn_kernel(const float* __restrict__ x) {
    __shared__ float px[Nn], py[Nn], pz[Nn];
    int b = blockIdx.y;
    const float* xb = x + (size_t)b * Nn * 3;
    for (int i = threadIdx.x; i < Nn; i += blockDim.x) {
        px[i] = xb[i*3+0]; py[i] = xb[i*3+1]; pz[i] = xb[i*3+2];
    }
    __syncthreads();
    int warp = threadIdx.x >> 5, lane = threadIdx.x & 31;
    int n = blockIdx.x * 8 + warp;
    float qx = px[n], qy = py[n], qz = pz[n];

    float dx = qx - px[lane], dy = qy - py[lane], dz = qz - pz[lane];
    float best_d = dx*dx + dy*dy + dz*dz;
    int   best_i = lane;
    float thr = best_d;
    #pragma unroll
    for (int off = 16; off; off >>= 1) thr = fmaxf(thr, __shfl_xor_sync(~0u, thr, off));
    int thr_lane = __ffs(__ballot_sync(~0u, best_d == thr)) - 1;

    for (int j0 = 32; j0 < Nn; j0 += 32) {
        int j = j0 + lane;
        dx = qx - px[j]; dy = qy - py[j]; dz = qz - pz[j];
        float d2 = dx*dx + dy*dy + dz*dz;
        unsigned mask = __ballot_sync(~0u, d2 < thr);
        while (mask) {
            int src = __ffs(mask) - 1; mask &= mask - 1;
            float cd = __shfl_sync(~0u, d2, src);
            if (cd < thr) {
                if (lane == thr_lane) { best_d = cd; best_i = j0 + src; }
                float m = best_d;
                #pragma unroll
                for (int off = 16; off; off >>= 1)
                    m = fmaxf(m, __shfl_xor_sync(~0u, m, off));
                thr = m;
                thr_lane = __ffs(__ballot_sync(~0u, best_d == m)) - 1;
            }
        }
    }
    g_src[(b * Nn + n) * Kk + lane] = best_i;
}

// ---------------- per-edge geometry ----------------
__global__ void geom_kernel(const float* __restrict__ x) {
    int gid = blockIdx.x * blockDim.x + threadIdx.x;
    if (gid >= Mm * Kk) return;
    int m = gid / Kk;
    int b = m / Nn, n = m % Nn;
    int s = g_src[gid];
    const float* xb = x + (size_t)b * Nn * 3;
    float vx = xb[n*3+0] - xb[s*3+0];
    float vy = xb[n*3+1] - xb[s*3+1];
    float vz = xb[n*3+2] - xb[s*3+2];
    float r = sqrtf(vx*vx + vy*vy + vz*vz);
    float xc = 10.0f - 5.0f * r;
    float cut = (xc > 0.0f) ? 1.4f * exp_fast(-fast_rcp(xc)) : 0.0f;
    g_cutb[gid] = cut;
    float inv = 1.0f / fmaxf(r, 1e-9f);
    float ux = vx * inv, uy = vy * inv, uz = vz * inv;
    const float s3 = 1.7320508075688772f;
    const float s15 = 3.872983346207417f;
    const float h5 = 1.118033988749895f;
    const float h15 = 1.9364916731037085f;
    float* sh = g_sh + (size_t)gid * SHDc;
    sh[0] = 1.0f;
    sh[1] = s3 * ux; sh[2] = s3 * uy; sh[3] = s3 * uz;
    sh[4] = s15 * ux * uy;
    sh[5] = s15 * uy * uz;
    sh[6] = h5 * (3.0f * uz * uz - 1.0f);
    sh[7] = s15 * ux * uz;
    sh[8] = h15 * (ux * ux - uy * uy);
    const float ISTEP = 15.5f;
    const float RBFC  = 5.656854249492381f * 0.95f / 1.12f;
    float base = r * ISTEP;
    int i0 = (int)floorf(base) - 3;
    i0 = max(0, min(24, i0));
    g_win[gid] = i0;
    float rb[NBc];
    #pragma unroll
    for (int ii = 0; ii < NBc; ii++) {
        float d = base - (float)ii;
        rb[ii] = exp_fast(-d * d) * RBFC * cut;
    }
    float4* dst = (float4*)(g_rbf + (size_t)gid * NBc);
    #pragma unroll
    for (int u = 0; u < 8; u++)
        dst[u] = make_float4(rb[u*4], rb[u*4+1], rb[u*4+2], rb[u*4+3]);
}

// ---------------- node embedding ----------------
__global__ void embed_kernel(const float* __restrict__ y, const float* __restrict__ t,
                             const float* __restrict__ W_embed) {
    __shared__ float in[3 + TDIMc];
    int m = blockIdx.x;
    int b = m / Nn;
    int tid = threadIdx.x;
    if (tid < 3) in[tid] = y[(size_t)m * 3 + tid];
    else if (tid < 3 + TDIMc) in[tid] = t[b * TDIMc + (tid - 3)];
    __syncthreads();
    float acc = 0.0f;
    #pragma unroll
    for (int i = 0; i < 3 + TDIMc; i++) acc += in[i] * W_embed[i * Dd + tid];
    g_node[(size_t)m * Dd + tid] = acc;
}

// ---------------- tpart ----------------
__global__ void tpart_kernel(const float* __restrict__ t, const float* __restrict__ Wk1,
                             const float* __restrict__ bk1) {
    int l = blockIdx.x / Bb, b = blockIdx.x % Bb;
    int j = threadIdx.x;
    float acc = bk1[l * HIDc + j];
    #pragma unroll
    for (int i = 0; i < TDIMc; i++)
        acc += t[b * TDIMc + i] * Wk1[((size_t)l * EINc + 32 + i) * HIDc + j];
    g_tpart[(l * Bb + b) * HIDc + j] = acc;
}

// ---------------- pack weights -> tf32 ----------------
__global__ void pack_kernel(const float* __restrict__ Wq, const float* __restrict__ Wv,
                            const float* __restrict__ Wk1, const float* __restrict__ Wo) {
    int i = blockIdx.x * 256 + threadIdx.x;
    const int SZ1 = Lc * 256 * 512;
    const int SZ2 = Lc * 128 * 256;
    if (i < SZ1) {
        int l = i / (256 * 512);
        int r = (i >> 9) & 255;
        int n = i & 511;
        float v = (n < 256) ? Wq[((size_t)l * 256 + r) * 256 + n]
                            : Wv[((size_t)l * (Dd + SHDc) + r) * 256 + (n - 256)];
        g_wcat1[i] = f2tf32(v);
    } else if (i < SZ1 + SZ2) {
        int j = i - SZ1;
        int l = j / (128 * 256);
        int r = (j >> 8) & 127;
        int n = j & 255;
        int row = (n < 128) ? (48 + r) : (176 + r);
        g_wcat2[j] = f2tf32(Wk1[((size_t)l * EINc + row) * HIDc + (n & 127)]);
    } else {
        int j = i - SZ1 - SZ2;
        if (j < 3 * 256 * 256) g_wcat3[j] = f2tf32(Wo[j]);
    }
}

// ---------------- TF32 TC GEMM, register-prefetch pipelined ----------------
__global__ void __launch_bounds__(256, 2)
gemm_tc(const float* __restrict__ A, int lda,
        const uint32_t* __restrict__ W, int ldw,
        float* __restrict__ C, int ldc, int Kd,
        const float* __restrict__ resid, int actmode) {
    __shared__ uint32_t sA[32 * 132];
    __shared__ uint32_t sB[32 * 132];
    int m0 = blockIdx.x * 128, n0 = blockIdx.y * 128;
    int tid = threadIdx.x, lane = tid & 31, wid = tid >> 5;
    int wm = (wid & 1) * 64, wn = (wid >> 1) * 32;
    int gp = lane >> 2, tg = lane & 3;

    int amm[4], akq[4], bkk[4], bnq[4];
    #pragma unroll
    for (int u = 0; u < 4; u++) {
        int id = tid + u * 256;
        amm[u] = id >> 3; akq[u] = (id & 7) * 4;
        bkk[u] = id >> 5; bnq[u] = (id & 31) * 4;
    }

    float c[4][4][4];
    #pragma unroll
    for (int i = 0; i < 4; i++)
        #pragma unroll
        for (int j = 0; j < 4; j++)
            #pragma unroll
            for (int r = 0; r < 4; r++) c[i][j][r] = 0.0f;

    float4 pa[4];
    uint4  pb[4];
    #pragma unroll
    for (int u = 0; u < 4; u++) {
        pa[u] = *(const float4*)&A[(size_t)(m0 + amm[u]) * lda + akq[u]];
        pb[u] = *(const uint4*)&W[(size_t)bkk[u] * ldw + n0 + bnq[u]];
    }

    for (int kt = 0; kt < Kd; kt += 32) {
        #pragma unroll
        for (int u = 0; u < 4; u++) {
            sA[(akq[u] + 0) * 132 + amm[u]] = f2tf32(pa[u].x);
            sA[(akq[u] + 1) * 132 + amm[u]] = f2tf32(pa[u].y);
            sA[(akq[u] + 2) * 132 + amm[u]] = f2tf32(pa[u].z);
            sA[(akq[u] + 3) * 132 + amm[u]] = f2tf32(pa[u].w);
            *(uint4*)&sB[bkk[u] * 132 + bnq[u]] = pb[u];
        }
        __syncthreads();
        if (kt + 32 < Kd) {
            #pragma unroll
            for (int u = 0; u < 4; u++) {
                pa[u] = *(const float4*)&A[(size_t)(m0 + amm[u]) * lda + kt + 32 + akq[u]];
                pb[u] = *(const uint4*)&W[(size_t)(kt + 32 + bkk[u]) * ldw + n0 + bnq[u]];
            }
        }
        #pragma unroll
        for (int ka = 0; ka < 4; ka++) {
            int kb = ka * 8;
            uint32_t bf[4][2];
            #pragma unroll
            for (int na = 0; na < 4; na++) {
                bf[na][0] = sB[(kb + tg) * 132 + wn + na * 8 + gp];
                bf[na][1] = sB[(kb + tg + 4) * 132 + wn + na * 8 + gp];
            }
            #pragma unroll
            for (int ma = 0; ma < 4; ma++) {
                int mb = wm + ma * 16 + gp;
                uint32_t a0 = sA[(kb + tg) * 132 + mb];
                uint32_t a1 = sA[(kb + tg) * 132 + mb + 8];
                uint32_t a2 = sA[(kb + tg + 4) * 132 + mb];
                uint32_t a3 = sA[(kb + tg + 4) * 132 + mb + 8];
                #pragma unroll
                for (int na = 0; na < 4; na++)
                    mma_tf32(c[ma][na], a0, a1, a2, a3, bf[na][0], bf[na][1]);
            }
        }
        __syncthreads();
    }

    #pragma unroll
    for (int ma = 0; ma < 4; ma++) {
        int row = m0 + wm + ma * 16 + gp;
        #pragma unroll
        for (int na = 0; na < 4; na++) {
            int col = n0 + wn + na * 8 + 2 * tg;
            #pragma unroll
            for (int half = 0; half < 2; half++) {
                int rr = row + half * 8;
                float v0 = c[ma][na][half * 2 + 0];
                float v1 = c[ma][na][half * 2 + 1];
                if (actmode == 1) {
                    float2 rs = *(const float2*)&resid[(size_t)rr * ldc + col];
                    v0 += rs.x; v1 += rs.y;
                    if (col < 64)       { v0 = gelu_fast(v0); v1 = gelu_fast(v1); }
                    else if (col < 128) { v0 = tanh_fast(v0); v1 = tanh_fast(v1); }
                }
                float2 o = make_float2(v0, v1);
                *(float2*)&C[(size_t)rr * ldc + col] = o;
            }
        }
    }
}

// ---------------- qk on tensor cores ----------------
__global__ void qk_tc(const float* __restrict__ Wk2, int l) {
    __shared__ uint32_t sA[32 * 132];
    __shared__ uint32_t sB[32 * 132];
    int m0 = blockIdx.x * 128;
    int h  = blockIdx.y;
    int tid = threadIdx.x, lane = tid & 31, wid = tid >> 5;
    int wm = (wid & 1) * 64, wn = (wid >> 1) * 32;
    int gp = lane >> 2, tg = lane & 3;
    const float* W = Wk2 + (size_t)l * HIDc * Dd;

    #pragma unroll
    for (int u = 0; u < 4; u++) {
        int id = tid + u * 256;
        int mm = id >> 3, kq = (id & 7) * 4;
        float4 v = *(const float4*)&g_qv[(size_t)(m0 + mm) * 512 + h * 32 + kq];
        sA[(kq + 0) * 132 + mm] = f2tf32(v.x);
        sA[(kq + 1) * 132 + mm] = f2tf32(v.y);
        sA[(kq + 2) * 132 + mm] = f2tf32(v.z);
        sA[(kq + 3) * 132 + mm] = f2tf32(v.w);
    }
    #pragma unroll
    for (int u = 0; u < 4; u++) {
        int id = tid + u * 256;
        int j = id >> 3, kq = (id & 7) * 4;
        float4 v = *(const float4*)&W[(size_t)j * 256 + h * 32 + kq];
        sB[(kq + 0) * 132 + j] = f2tf32(v.x);
        sB[(kq + 1) * 132 + j] = f2tf32(v.y);
        sB[(kq + 2) * 132 + j] = f2tf32(v.z);
        sB[(kq + 3) * 132 + j] = f2tf32(v.w);
    }
    __syncthreads();

    float c[4][4][4];
    #pragma unroll
    for (int i = 0; i < 4; i++)
        #pragma unroll
        for (int j = 0; j < 4; j++)
            #pragma unroll
            for (int r = 0; r < 4; r++) c[i][j][r] = 0.0f;

    #pragma unroll
    for (int ka = 0; ka < 4; ka++) {
        int kb = ka * 8;
        uint32_t bf[4][2];
        #pragma unroll
        for (int na = 0; na < 4; na++) {
            bf[na][0] = sB[(kb + tg) * 132 + wn + na * 8 + gp];
            bf[na][1] = sB[(kb + tg + 4) * 132 + wn + na * 8 + gp];
        }
        #pragma unroll
        for (int ma = 0; ma < 4; ma++) {
            int mb = wm + ma * 16 + gp;
            uint32_t a0 = sA[(kb + tg) * 132 + mb];
            uint32_t a1 = sA[(kb + tg) * 132 + mb + 8];
            uint32_t a2 = sA[(kb + tg + 4) * 132 + mb];
            uint32_t a3 = sA[(kb + tg + 4) * 132 + mb + 8];
            #pragma unroll
            for (int na = 0; na < 4; na++)
                mma_tf32(c[ma][na], a0, a1, a2, a3, bf[na][0], bf[na][1]);
        }
    }

    #pragma unroll
    for (int ma = 0; ma < 4; ma++) {
        int row = m0 + wm + ma * 16 + gp;
        #pragma unroll
        for (int na = 0; na < 4; na++) {
            int col = wn + na * 8 + 2 * tg;
            #pragma unroll
            for (int half = 0; half < 2; half++) {
                int rr = row + half * 8;
                float2 o = make_float2(c[ma][na][half * 2 + 0], c[ma][na][half * 2 + 1]);
                *(float2*)&g_qk[(size_t)rr * 1024 + h * 128 + col] = o;
            }
        }
    }
}

// ---------------- fused edge kernel (R10 dataflow + warp-parallel softmax/asum) ------
__global__ void edge_kernel(const float* __restrict__ Wk1, const float* __restrict__ Wv,
                            int l) {
    __shared__ float s_wk1[32 * 128];   // [ii][j]
    __shared__ float s_rbf[32 * 36];    // [k][ii]
    __shared__ float s_qk [8 * 132];    // [h][j]
    __shared__ float s_al [32 * 8];     // [k][h]
    __shared__ float s_shl[32 * 9];     // [k][s]
    __shared__ float s_wvsh[9 * 256];   // [s][d]
    __shared__ float s_asum[Hh * SHDc]; // [h][s]
    __shared__ float s_base[128];
    __shared__ float s_cut[32];
    __shared__ int   s_id[32];
    __shared__ int   s_i0[32];

    int m = blockIdx.x;
    int b = m >> 10;
    int tid = threadIdx.x;
    const float* Wk1l = Wk1 + (size_t)l * EINc * HIDc;
    const float* WvSh = Wv + ((size_t)l * (Dd + SHDc) + Dd) * Dd;
    const float* tpl  = g_tpart + (l * Bb + b) * HIDc;

    if (tid < 32) {
        s_id[tid]  = g_src [m * 32 + tid];
        s_cut[tid] = g_cutb[m * 32 + tid];
        s_i0[tid]  = g_win [m * 32 + tid];
    }
    if (tid < 128) s_base[tid] = g_ss[(size_t)m * 256 + 128 + tid] + tpl[tid];
    for (int i = tid; i < 1024; i += 256) {
        int h = i >> 7, j = i & 127;
        s_qk[h * 132 + j] = g_qk[(size_t)m * 1024 + i];
    }
    for (int i = tid; i < 32 * SHDc; i += 256) s_shl[i] = g_sh[(size_t)m * 32 * SHDc + i];
    {
        float4 v = *(const float4*)&g_rbf[(size_t)m * 1024 + tid * 4];
        int k = tid >> 3, ii0 = (tid & 7) * 4;
        *(float4*)&s_rbf[k * 36 + ii0] = v;
    }
    #pragma unroll
    for (int u = 0; u < 4; u++) {
        int idx = (tid + u * 256) * 4;
        *(float4*)&s_wk1[idx] = *(const float4*)&Wk1l[idx];
    }
    #pragma unroll
    for (int u = 0; u < 3; u++) {
        int i = tid + u * 256;
        if (i < 576) *(float4*)&s_wvsh[i * 4] = *(const float4*)&WvSh[i * 4];
    }
    __syncthreads();

    int lane = tid & 31, wid = tid >> 5;
    int j0 = lane * 4, k0 = wid * 4;
    float acc[4][4];
    #pragma unroll
    for (int ki = 0; ki < 4; ki++) {
        int k = k0 + ki;
        int i0 = s_i0[k];
        float a0 = 0.0f, a1 = 0.0f, a2 = 0.0f, a3 = 0.0f;
        #pragma unroll
        for (int w = 0; w < WIN; w++) {
            int ii = i0 + w;
            float rb = s_rbf[k * 36 + ii];
            float4 wv = *(const float4*)&s_wk1[ii * 128 + j0];
            a0 = fmaf(rb, wv.x, a0);
            a1 = fmaf(rb, wv.y, a1);
            a2 = fmaf(rb, wv.z, a2);
            a3 = fmaf(rb, wv.w, a3);
        }
        acc[ki][0] = a0; acc[ki][1] = a1; acc[ki][2] = a2; acc[ki][3] = a3;
    }
    float qv4[8][4];
    #pragma unroll
    for (int h = 0; h < 8; h++)
        *(float4*)&qv4[h][0] = *(const float4*)&s_qk[h * 132 + j0];

    const float* ssB = g_ss + (size_t)b * Nn * 256;
    float4 base = *(const float4*)&s_base[j0];
    float v[32];
    #pragma unroll
    for (int ki = 0; ki < 4; ki++) {
        int k = k0 + ki;
        float4 sv = *(const float4*)&ssB[(size_t)s_id[k] * 256 + j0];
        float gl[4];
        gl[0] = gelu_fast(acc[ki][0] + sv.x + base.x);
        gl[1] = gelu_fast(acc[ki][1] + sv.y + base.y);
        gl[2] = gelu_fast(acc[ki][2] + sv.z + base.z);
        gl[3] = gelu_fast(acc[ki][3] + sv.w + base.w);
        #pragma unroll
        for (int h = 0; h < 8; h++) {
            float s = gl[0]*qv4[h][0] + gl[1]*qv4[h][1] + gl[2]*qv4[h][2] + gl[3]*qv4[h][3];
            v[ki * 8 + h] = s;
        }
    }
    #pragma unroll
    for (int s = 16; s >= 1; s >>= 1) {
        #pragma unroll
        for (int i = 0; i < s; i++) {
            float send = (lane & s) ? v[i] : v[i + s];
            float recv = __shfl_xor_sync(0xffffffffu, send, s);
            v[i] = ((lane & s) ? v[i + s] : v[i]) + recv;
        }
    }
    s_al[(k0 + (lane >> 3)) * 8 + (lane & 7)] = v[0] * 0.17677669529663687f;
    __syncthreads();

    // warp-parallel softmax + asum: warp h handles head h, lane = k
    {
        int h = wid;
        int k = lane;
        float logit = s_al[k * 8 + h];
        float mx = logit;
        #pragma unroll
        for (int off = 16; off; off >>= 1)
            mx = fmaxf(mx, __shfl_xor_sync(~0u, mx, off));
        float w = s_cut[k] * exp_fast(logit - mx);
        float sum = w;
        #pragma unroll
        for (int off = 16; off; off >>= 1)
            sum += __shfl_xor_sync(~0u, sum, off);
        float alpha = w * (1.0f / (sum + 1e-9f));
        s_al[k * 8 + h] = alpha;
        // asum[h][s] = sum_k alpha * sh[k][s], same warp, registers
        #pragma unroll
        for (int s = 0; s < SHDc; s++) {
            float p = alpha * s_shl[k * SHDc + s];
            #pragma unroll
            for (int off = 16; off; off >>= 1)
                p += __shfl_xor_sync(~0u, p, off);
            if (lane == 0) s_asum[h * SHDc + s] = p;
        }
    }
    __syncthreads();

    // agg[d] = sum_k alpha[k,h(d)]*vn[src[k],d] + sum_s asum[h,s]*WvSh[s,d]
    {
        int d = tid;
        int h = d >> 5;
        const float* vnB = g_qv + (size_t)b * Nn * 512 + 256;
        float acc2 = 0.0f;
        #pragma unroll 8
        for (int k = 0; k < 32; k++)
            acc2 += s_al[k * 8 + h] * vnB[(size_t)s_id[k] * 512 + d];
        float proj = 0.0f;
        #pragma unroll
        for (int s = 0; s < SHDc; s++) proj += s_asum[h * SHDc + s] * s_wvsh[s * 256 + d];
        g_agg[(size_t)m * Dd + d] = acc2 + proj;
    }
}

// ---------------- final projection ----------------
__global__ void final_kernel(const float* __restrict__ Wo_out, float* __restrict__ out) {
    int gid = blockIdx.x * blockDim.x + threadIdx.x;
    if (gid >= Mm * 3) return;
    int m = gid / 3, c = gid % 3;
    const float* a = g_agg + (size_t)m * Dd;
    float acc = 0.0f;
    #pragma unroll 8
    for (int j = 0; j < Dd; j++) acc += a[j] * Wo_out[j * 3 + c];
    out[gid] = acc;
}

// ---------------- host orchestration ----------------
extern "C" void kernel_launch(void* const* d_in, const int* in_sizes, int n_in,
                              void* d_out, int out_size) {
    const float* x       = (const float*)d_in[0];
    const float* y       = (const float*)d_in[1];
    const float* t       = (const float*)d_in[2];
    const float* W_embed = (const float*)d_in[3];
    const float* Wk1     = (const float*)d_in[4];
    const float* bk1     = (const float*)d_in[5];
    const float* Wk2     = (const float*)d_in[6];
    const float* Wq      = (const float*)d_in[7];
    const float* Wv      = (const float*)d_in[8];
    const float* Wo      = (const float*)d_in[9];
    const float* Wo_out  = (const float*)d_in[10];
    float* out = (float*)d_out;

    float *p_node, *p_qv, *p_ss, *p_agg;
    uint32_t *p_wcat1, *p_wcat2, *p_wcat3;
    cudaGetSymbolAddress((void**)&p_node,  g_node);
    cudaGetSymbolAddress((void**)&p_qv,    g_qv);
    cudaGetSymbolAddress((void**)&p_ss,    g_ss);
    cudaGetSymbolAddress((void**)&p_agg,   g_agg);
    cudaGetSymbolAddress((void**)&p_wcat1, g_wcat1);
    cudaGetSymbolAddress((void**)&p_wcat2, g_wcat2);
    cudaGetSymbolAddress((void**)&p_wcat3, g_wcat3);

    const int PACKN = Lc * 256 * 512 + Lc * 128 * 256 + 3 * 256 * 256;

    embed_kernel<<<Mm, Dd>>>(y, t, W_embed);                                   // 1
    pack_kernel<<<(PACKN + 255) / 256, 256>>>(Wq, Wv, Wk1, Wo);                // 2
    tpart_kernel<<<Lc * Bb, HIDc>>>(t, Wk1, bk1);                              // 3
    knn_kernel<<<dim3(Nn / 8, Bb), 256>>>(x);                                  // 4
    geom_kernel<<<(Mm * Kk + 255) / 256, 256>>>(x);                            // 5

    for (int l = 0; l < Lc; l++) {
        gemm_tc<<<dim3(Mm / 128, 512 / 128), 256>>>(
            p_node, Dd, p_wcat1 + (size_t)l * 256 * 512, 512,
            p_qv, 512, 256, nullptr, 0);
        gemm_tc<<<dim3(Mm / 128, 256 / 128), 256>>>(
            p_node, Dd, p_wcat2 + (size_t)l * 128 * 256, 256,
            p_ss, 256, 128, nullptr, 0);
        qk_tc<<<dim3(Mm / 128, Hh), 256>>>(Wk2, l);
        edge_kernel<<<Mm, 256>>>(Wk1, Wv, l);

        if (l < Lc - 1) {
            gemm_tc<<<dim3(Mm / 128, 256 / 128), 256>>>(
                p_agg, Dd, p_wcat3 + (size_t)l * 256 * 256, 256,
                p_node, Dd, 256, p_node, 1);
        } else {
            final_kernel<<<(Mm * 3 + 255) / 256, 256>>>(Wo_out, out);
        }
    }
}